// round 13
// baseline (speedup 1.0000x reference)
#include <cuda_runtime.h>

// Problem constants
constexpr int cB = 128, cT = 256, cA = 16, cL = 256, cS = 32, cD = 512;
constexpr int cBT = cB * cT;

// ---------------------------------------------------------------------------
// Scratch (device globals; no runtime allocation allowed)
// ---------------------------------------------------------------------------
__device__ float g_hidden[(long)cBT * 512];  // Qo during scan; MLP hidden after
__device__ float g_hq[cB * 512];             // per-step posterior hidden
__device__ volatile int g_bar_count;         // grid barrier (self-resetting)
__device__ volatile int g_bar_gen;

// Software grid barrier. Valid because grid (128) <= SM count -> all CTAs
// co-resident. Generation counter persists across launches (equality test),
// count returns to 0 after every barrier -> deterministic across replays.
__device__ __forceinline__ void grid_sync() {
    __syncthreads();
    if (threadIdx.x == 0) {
        __threadfence();
        int gen = g_bar_gen;
        if (atomicAdd((int*)&g_bar_count, 1) == (int)gridDim.x - 1) {
            g_bar_count = 0;
            __threadfence();
            g_bar_gen = gen + 1;
        } else {
            while (g_bar_gen == gen) { __nanosleep(32); }
        }
        __threadfence();
    }
    __syncthreads();
}

// ---------------------------------------------------------------------------
// Persistent scan kernel: the whole 256-step recurrence in ONE launch.
// grid = 128 CTAs x 256 threads. 3 phases + 3 grid syncs per step.
// ---------------------------------------------------------------------------
__global__ __launch_bounds__(256) void rssm_scan(
    const float* __restrict__ actions, const float* __restrict__ eps,
    const float* __restrict__ h0, const float* __restrict__ z0,
    const float* __restrict__ Wih, const float* __restrict__ Whh,
    const float* __restrict__ bih, const float* __restrict__ bhh,
    const float* __restrict__ qW1, const float* __restrict__ qW2,
    const float* __restrict__ qb2,
    float* __restrict__ h_seq, float* __restrict__ z_seq,
    float* __restrict__ pos_mu, float* __restrict__ pos_ls)
{
    __shared__ float sm[1664];
    const int c = blockIdx.x;
    const int tid = threadIdx.x;

    for (int t = 0; t < cT; t++) {
        const float* hprev = t ? (h_seq + (long)(t - 1) * cD) : h0;
        const long   ldh   = t ? (long)cT * cD : cD;
        const float* zprev = t ? (z_seq + (long)(t - 1) * cS) : z0;
        const long   ldz   = t ? (long)cT * cS : cS;

        // ================= Phase AB: GRU gates (gh + gi fused) -> h_t ======
        {
            float* As = sm;          // [32][17]  (padded)
            float* Ws = sm + 544;    // [3][16][16]
            const int d  = tid & 15, bg = tid >> 4;   // 16 d x 16 b-groups
            const int dt = c & 31,   bt = c >> 5;     // 32 d-tiles x 4 b-tiles
            const int b0 = bt * 32,  d0 = dt * 16;
            const int lb = tid >> 4, lk = tid & 15;   // load coords
            const int wk = tid >> 4, wd = tid & 15;

            float aR[2] = {0, 0}, aZ[2] = {0, 0};
            float aNH[2] = {0, 0}, aNI[2] = {0, 0};   // n gate: hidden/input SPLIT

            // gh part: K=512 over Whh
            for (int ch = 0; ch < 32; ch++) {
                As[lb * 17 + lk]        = hprev[(long)(b0 + lb) * ldh + ch * 16 + lk];
                As[(lb + 16) * 17 + lk] = hprev[(long)(b0 + lb + 16) * ldh + ch * 16 + lk];
                const float* Wp = Whh + (long)(ch * 16 + wk) * 1536 + d0 + wd;
                Ws[wk * 16 + wd]       = Wp[0];
                Ws[256 + wk * 16 + wd] = Wp[512];
                Ws[512 + wk * 16 + wd] = Wp[1024];
                __syncthreads();
                #pragma unroll
                for (int kk = 0; kk < 16; kk++) {
                    float w0 = Ws[kk * 16 + d];
                    float w1 = Ws[256 + kk * 16 + d];
                    float w2 = Ws[512 + kk * 16 + d];
                    float a0 = As[(bg * 2) * 17 + kk];
                    float a1 = As[(bg * 2 + 1) * 17 + kk];
                    aR[0] += a0 * w0; aZ[0] += a0 * w1; aNH[0] += a0 * w2;
                    aR[1] += a1 * w0; aZ[1] += a1 * w1; aNH[1] += a1 * w2;
                }
                __syncthreads();
            }
            // gi part: K=48 over Wih, x = [z_prev (32) | action_t (16)]
            for (int ch = 0; ch < 3; ch++) {
                float v0, v1;
                if (ch < 2) {
                    v0 = zprev[(long)(b0 + lb) * ldz + ch * 16 + lk];
                    v1 = zprev[(long)(b0 + lb + 16) * ldz + ch * 16 + lk];
                } else {
                    v0 = actions[(long)(b0 + lb) * (cT * cA) + (long)t * cA + lk];
                    v1 = actions[(long)(b0 + lb + 16) * (cT * cA) + (long)t * cA + lk];
                }
                As[lb * 17 + lk] = v0;
                As[(lb + 16) * 17 + lk] = v1;
                const float* Wp = Wih + (long)(ch * 16 + wk) * 1536 + d0 + wd;
                Ws[wk * 16 + wd]       = Wp[0];
                Ws[256 + wk * 16 + wd] = Wp[512];
                Ws[512 + wk * 16 + wd] = Wp[1024];
                __syncthreads();
                #pragma unroll
                for (int kk = 0; kk < 16; kk++) {
                    float w0 = Ws[kk * 16 + d];
                    float w1 = Ws[256 + kk * 16 + d];
                    float w2 = Ws[512 + kk * 16 + d];
                    float a0 = As[(bg * 2) * 17 + kk];
                    float a1 = As[(bg * 2 + 1) * 17 + kk];
                    aR[0] += a0 * w0; aZ[0] += a0 * w1; aNI[0] += a0 * w2;
                    aR[1] += a1 * w0; aZ[1] += a1 * w1; aNI[1] += a1 * w2;
                }
                __syncthreads();
            }
            const int dg = d0 + d;
            const float br  = bih[dg]        + bhh[dg];
            const float bz  = bih[512 + dg]  + bhh[512 + dg];
            const float bni = bih[1024 + dg];
            const float bnh = bhh[1024 + dg];
            #pragma unroll
            for (int i = 0; i < 2; i++) {
                const int b = b0 + bg * 2 + i;
                float r = 1.0f / (1.0f + expf(-(aR[i] + br)));
                float u = 1.0f / (1.0f + expf(-(aZ[i] + bz)));
                float n = tanhf(aNI[i] + bni + r * (aNH[i] + bnh));
                float hp = hprev[(long)b * ldh + dg];
                h_seq[(long)b * (cT * cD) + (long)t * cD + dg] = (1.0f - u) * n + u * hp;
            }
        }
        grid_sync();

        // ================= Phase C: hq = relu(h_t @ qW1 + Qo) ==============
        {
            float* Ah = sm;          // [16][17]
            float* Wq = sm + 272;    // [16][32]
            const int n_l = tid & 31, bg = tid >> 5;   // 32 n x 8 b-groups
            const int nt = c & 15, bt = c >> 4;        // 16 n-tiles x 8 b-tiles
            const int b0 = bt * 16, n0 = nt * 32;
            const int lb = tid >> 4, lk = tid & 15;
            float acc0 = 0.0f, acc1 = 0.0f;

            for (int ch = 0; ch < 32; ch++) {
                Ah[lb * 17 + lk] =
                    h_seq[(long)(b0 + lb) * (cT * cD) + (long)t * cD + ch * 16 + lk];
                {
                    int k = tid >> 5, n = tid & 31;
                    Wq[k * 32 + n]       = qW1[(long)(ch * 16 + k) * 512 + n0 + n];
                    Wq[(k + 8) * 32 + n] = qW1[(long)(ch * 16 + k + 8) * 512 + n0 + n];
                }
                __syncthreads();
                #pragma unroll
                for (int kk = 0; kk < 16; kk++) {
                    float w = Wq[kk * 32 + n_l];
                    acc0 += Ah[(bg * 2) * 17 + kk] * w;
                    acc1 += Ah[(bg * 2 + 1) * 17 + kk] * w;
                }
                __syncthreads();
            }
            const float* Qo = g_hidden;
            const int bA = b0 + bg * 2;
            float q0 = Qo[(long)bA * (cT * 512) + (long)t * 512 + n0 + n_l];
            float q1 = Qo[(long)(bA + 1) * (cT * 512) + (long)t * 512 + n0 + n_l];
            g_hq[bA * 512 + n0 + n_l]       = fmaxf(acc0 + q0, 0.0f);
            g_hq[(bA + 1) * 512 + n0 + n_l] = fmaxf(acc1 + q1, 0.0f);
        }
        grid_sync();

        // ================= Phase D: q2 + clip + sample -> z_t ==============
        if (c < 64) {
            float* Hs0 = sm;          // 512
            float* Hs1 = sm + 512;    // 512
            float* Ps  = sm + 1024;   // 512 partials + 128 post
            const int b0 = c * 2;
            for (int i = tid; i < 512; i += 256) {
                Hs0[i] = g_hq[b0 * 512 + i];
                Hs1[i] = g_hq[(b0 + 1) * 512 + i];
            }
            __syncthreads();
            const int j = tid & 63, part = tid >> 6;
            float a0 = 0.0f, a1 = 0.0f;
            const float* Wp = qW2 + (long)(part * 128) * 64 + j;
            #pragma unroll 16
            for (int k = 0; k < 128; k++) {
                float w = Wp[(long)k * 64];
                a0 += Hs0[part * 128 + k] * w;
                a1 += Hs1[part * 128 + k] * w;
            }
            Ps[part * 128 + j]      = a0;
            Ps[part * 128 + 64 + j] = a1;
            __syncthreads();
            if (tid < 64) {
                float v0 = qb2[tid], v1 = qb2[tid];
                #pragma unroll
                for (int p = 0; p < 4; p++) {
                    v0 += Ps[p * 128 + tid];
                    v1 += Ps[p * 128 + 64 + tid];
                }
                Ps[512 + tid]      = v0;
                Ps[512 + 64 + tid] = v1;
            }
            __syncthreads();
            if (tid < 64) {
                int row = tid >> 5, jj = tid & 31;
                int b = b0 + row;
                float mu = Ps[512 + row * 64 + jj];
                float ls = fminf(fmaxf(Ps[512 + row * 64 + 32 + jj], -10.0f), 2.0f);
                long o = (long)b * (cT * cS) + (long)t * cS + jj;
                pos_mu[o] = mu;
                pos_ls[o] = ls;
                z_seq[o]  = mu + eps[o] * expf(ls);
            }
        }
        grid_sync();
    }
}

// ---------------------------------------------------------------------------
// Generic fp32 GEMM, 64x64 tile, BK=16, 256 threads, 4x4 micro-tile.
// A(m,k) = k<K1 ? A1[m*lda1+k] : A2[m*lda2+k-K1]
// epi=0: C[gm*ldc+gn] = v ; epi=2 (N==64): cols<32 -> C (mu),
//        cols>=32 -> C2 = clip(v,-10,2)
// ---------------------------------------------------------------------------
__global__ __launch_bounds__(256) void gemm64(
    const float* __restrict__ A1, int lda1, int K1,
    const float* __restrict__ A2, int lda2,
    const float* __restrict__ W, int ldw,
    const float* __restrict__ bias,
    float* __restrict__ C, int ldc,
    float* __restrict__ C2,
    int K, int relu, int epi)
{
    __shared__ float As[16][64];
    __shared__ float Ws[16][64];
    const int tid = threadIdx.x;
    const int tn = tid & 15, tm = tid >> 4;
    const int bm = blockIdx.y * 64, bn = blockIdx.x * 64;

    float acc[4][4] = {};

    for (int k0 = 0; k0 < K; k0 += 16) {
        #pragma unroll
        for (int e = 0; e < 4; e++) {
            int idx = tid + e * 256;
            int m = idx >> 4, k = idx & 15;
            int gk = k0 + k;
            float v = (gk < K1) ? A1[(long)(bm + m) * lda1 + gk]
                                : A2[(long)(bm + m) * lda2 + (gk - K1)];
            As[k][m] = v;
        }
        #pragma unroll
        for (int e = 0; e < 4; e++) {
            int idx = tid + e * 256;
            int k = idx >> 6, n = idx & 63;
            Ws[k][n] = W[(long)(k0 + k) * ldw + bn + n];
        }
        __syncthreads();
        #pragma unroll
        for (int kk = 0; kk < 16; kk++) {
            float4 a4 = *reinterpret_cast<const float4*>(&As[kk][tm * 4]);
            float4 w4 = *reinterpret_cast<const float4*>(&Ws[kk][tn * 4]);
            float av[4] = {a4.x, a4.y, a4.z, a4.w};
            float wv[4] = {w4.x, w4.y, w4.z, w4.w};
            #pragma unroll
            for (int i = 0; i < 4; i++)
                #pragma unroll
                for (int j = 0; j < 4; j++)
                    acc[i][j] += av[i] * wv[j];
        }
        __syncthreads();
    }

    #pragma unroll
    for (int i = 0; i < 4; i++) {
        int gm = bm + tm * 4 + i;
        #pragma unroll
        for (int j = 0; j < 4; j++) {
            int gn = bn + tn * 4 + j;
            float v = acc[i][j];
            if (bias) v += bias[gn];
            if (relu) v = fmaxf(v, 0.0f);
            if (epi == 0) {
                C[(long)gm * ldc + gn] = v;
            } else {
                if (gn < 32) C[(long)gm * 32 + gn] = v;
                else C2[(long)gm * 32 + (gn - 32)] = fminf(fmaxf(v, -10.0f), 2.0f);
            }
        }
    }
}

// ---------------------------------------------------------------------------
// Matvec for reward/done heads: out[r] = dot(H[r,:512], w) + b. Warp per row.
// ---------------------------------------------------------------------------
__global__ __launch_bounds__(256) void matvec512(
    const float* __restrict__ Hd, const float* __restrict__ w,
    const float* __restrict__ bptr, float* __restrict__ out)
{
    const int warp = threadIdx.x >> 5, lane = threadIdx.x & 31;
    const int r = blockIdx.x * 8 + warp;
    const float* hr = Hd + (long)r * 512;
    float s = 0.0f;
    #pragma unroll
    for (int k0 = lane * 4; k0 < 512; k0 += 128) {
        float4 h4 = *reinterpret_cast<const float4*>(&hr[k0]);
        float4 w4 = *reinterpret_cast<const float4*>(&w[k0]);
        s += h4.x * w4.x + h4.y * w4.y + h4.z * w4.z + h4.w * w4.w;
    }
    #pragma unroll
    for (int o = 16; o > 0; o >>= 1) s += __shfl_down_sync(0xffffffffu, s, o);
    if (lane == 0) out[r] = s + bptr[0];
}

// ---------------------------------------------------------------------------
// Host driver — 10 graph nodes total.
// ---------------------------------------------------------------------------
extern "C" void kernel_launch(void* const* d_in, const int* in_sizes, int n_in,
                              void* d_out, int out_size)
{
    const float* actions = (const float*)d_in[0];
    const float* obs     = (const float*)d_in[1];
    const float* eps     = (const float*)d_in[2];
    const float* h0      = (const float*)d_in[3];
    const float* z0      = (const float*)d_in[4];
    const float* Wih     = (const float*)d_in[5];
    const float* Whh     = (const float*)d_in[6];
    const float* bih     = (const float*)d_in[7];
    const float* bhh     = (const float*)d_in[8];
    const float* pW1     = (const float*)d_in[9];
    const float* pb1     = (const float*)d_in[10];
    const float* pW2     = (const float*)d_in[11];
    const float* pb2     = (const float*)d_in[12];
    const float* qW1     = (const float*)d_in[13];
    const float* qb1     = (const float*)d_in[14];
    const float* qW2     = (const float*)d_in[15];
    const float* qb2     = (const float*)d_in[16];
    const float* oW1     = (const float*)d_in[17];
    const float* ob1     = (const float*)d_in[18];
    const float* oW2     = (const float*)d_in[19];
    const float* ob2     = (const float*)d_in[20];
    const float* rW1     = (const float*)d_in[21];
    const float* rb1     = (const float*)d_in[22];
    const float* rW2     = (const float*)d_in[23];
    const float* rb2     = (const float*)d_in[24];
    const float* dW1     = (const float*)d_in[25];
    const float* db1     = (const float*)d_in[26];
    const float* dW2     = (const float*)d_in[27];
    const float* db2     = (const float*)d_in[28];

    float* out    = (float*)d_out;
    float* h_seq  = out;                       // [B,T,512]
    float* z_seq  = h_seq  + (long)cBT * 512;  // [B,T,32]
    float* obs_p  = z_seq  + (long)cBT * 32;   // [B,T,256]
    float* rew_p  = obs_p  + (long)cBT * 256;  // [B,T]
    float* done_p = rew_p  + cBT;              // [B,T]
    float* pri_mu = done_p + cBT;              // [B,T,32]
    float* pri_ls = pri_mu + (long)cBT * 32;
    float* pos_mu = pri_ls + (long)cBT * 32;
    float* pos_ls = pos_mu + (long)cBT * 32;

    float* hidden;
    cudaGetSymbolAddress((void**)&hidden, g_hidden);

    // 1) Precompute Qo = obs_embeds @ qW1[512:768,:] + qb1  (M=BT,K=256,N=512)
    gemm64<<<dim3(512 / 64, cBT / 64), 256>>>(
        obs, cL, 256, nullptr, 0,
        qW1 + 512 * 512, 512, qb1,
        hidden, 512, nullptr, 256, 0, 0);

    // 2) Whole recurrence: ONE persistent kernel
    rssm_scan<<<128, 256>>>(actions, eps, h0, z0,
                            Wih, Whh, bih, bhh,
                            qW1, qW2, qb2,
                            h_seq, z_seq, pos_mu, pos_ls);

    // 3) Batched heads over all B*T rows
    // prior: hidden = relu(h_seq @ pW1 + pb1); stats = hidden @ pW2 + pb2
    gemm64<<<dim3(8, cBT / 64), 256>>>(
        h_seq, 512, 512, nullptr, 0, pW1, 512, pb1,
        hidden, 512, nullptr, 512, 1, 0);
    gemm64<<<dim3(1, cBT / 64), 256>>>(
        hidden, 512, 512, nullptr, 0, pW2, 64, pb2,
        pri_mu, 0, pri_ls, 512, 0, 2);

    // obs head: st = [h|z]
    gemm64<<<dim3(8, cBT / 64), 256>>>(
        h_seq, 512, 512, z_seq, 32, oW1, 512, ob1,
        hidden, 512, nullptr, 544, 1, 0);
    gemm64<<<dim3(4, cBT / 64), 256>>>(
        hidden, 512, 512, nullptr, 0, oW2, 256, ob2,
        obs_p, 256, nullptr, 512, 0, 0);

    // reward head
    gemm64<<<dim3(8, cBT / 64), 256>>>(
        h_seq, 512, 512, z_seq, 32, rW1, 512, rb1,
        hidden, 512, nullptr, 544, 1, 0);
    matvec512<<<cBT / 8, 256>>>(hidden, rW2, rb2, rew_p);

    // done head
    gemm64<<<dim3(8, cBT / 64), 256>>>(
        h_seq, 512, 512, z_seq, 32, dW1, 512, db1,
        hidden, 512, nullptr, 544, 1, 0);
    matvec512<<<cBT / 8, 256>>>(hidden, dW2, db2, done_p);
}